// round 2
// baseline (speedup 1.0000x reference)
#include <cuda_runtime.h>
#include <cstdint>

#define N_NODES 100000
#define N_EDGES 1600000
#define IN_CH   128
#define HID_CH  64
#define OUT_CH  32

// ---------------- scratch (static __device__ — no runtime allocation) ----------------
__device__ float g_deg [N_NODES];
__device__ float g_dinv[N_NODES];
__device__ int4  g_edge[N_EDGES];                         // {src*64, dst*64, coef_bits, 0}
__device__ float g_h1  [(size_t)N_NODES * HID_CH];        // layer-1 features (pre-agg, then relu'd)
__device__ float g_agg1[(size_t)N_NODES * HID_CH];        // layer-1 aggregation buffer
__device__ float g_h2  [(size_t)N_NODES * OUT_CH];        // layer-2 transformed features
__device__ int   g_idx64;                                 // 1 if edge_index is int64, 0 if int32

// ---------------- edge_index dtype detection ----------------
// Interpreted as int64: true int64 node ids are < N_NODES (high word 0).
// int32 data read as int64 packs two ids -> values >= 2^32 almost surely.
__global__ void k_detect(const void* ei, int n_elems) {
    __shared__ int bad;
    if (threadIdx.x == 0) bad = 0;
    __syncthreads();
    const long long* p = (const long long*)ei;
    long long m = (long long)n_elems / 2;   // safe byte bound for either dtype
    if (m > 4096) m = 4096;
    for (long long i = threadIdx.x; i < m; i += blockDim.x) {
        long long v = p[i];
        if (v < 0 || v >= N_NODES) bad = 1;
    }
    __syncthreads();
    if (threadIdx.x == 0) g_idx64 = bad ? 0 : 1;
}

__device__ __forceinline__ void load_edge(const void* ei, int e, int& s, int& d) {
    if (g_idx64) {
        const long long* p = (const long long*)ei;
        s = (int)p[e];
        d = (int)p[N_EDGES + e];
    } else {
        const int* p = (const int*)ei;
        s = p[e];
        d = p[N_EDGES + e];
    }
}

// ---------------- degree / normalization ----------------
__global__ void k_initdeg() {
    int i = blockIdx.x * blockDim.x + threadIdx.x;
    if (i < N_NODES) g_deg[i] = 1.0f;   // self-loop
}

__global__ void k_count(const void* ei) {
    int e = blockIdx.x * blockDim.x + threadIdx.x;
    if (e >= N_EDGES) return;
    int d;
    if (g_idx64) d = (int)((const long long*)ei)[N_EDGES + e];
    else         d = ((const int*)ei)[N_EDGES + e];
    atomicAdd(&g_deg[d], 1.0f);
}

__global__ void k_dinv() {
    int i = blockIdx.x * blockDim.x + threadIdx.x;
    if (i < N_NODES) g_dinv[i] = rsqrtf(g_deg[i]);
}

// Pack per-edge record: premultiplied row offsets for layer 1 (HID=64),
// layer 2 uses offset >> 1 (OUT=32). coef = dinv[src]*dinv[dst].
__global__ void k_edgeprep(const void* ei) {
    int e = blockIdx.x * blockDim.x + threadIdx.x;
    if (e >= N_EDGES) return;
    int s, d;
    load_edge(ei, e, s, d);
    float c = g_dinv[s] * g_dinv[d];
    g_edge[e] = make_int4(s * HID_CH, d * HID_CH, __float_as_int(c), 0);
}

// ---------------- GEMM1: h1 = x @ W1 ; agg1 = h1*dinv^2 + b1 ----------------
// 256 threads, 32 rows/block (N divisible by 32), 8 threads/row, 8 outputs/thread.
// W1 (32KB) staged in smem; x streamed via LDG.128 (broadcast across the 8 row-threads).
__global__ void __launch_bounds__(256) k_gemm1(const float* __restrict__ x,
                                               const float* __restrict__ W1,
                                               const float* __restrict__ b1) {
    __shared__ float Ws[IN_CH * HID_CH];   // [k][64], 32KB
    int tid = threadIdx.x;
    {
        const float4* W4 = (const float4*)W1;
        float4* Ws4 = (float4*)Ws;
        #pragma unroll
        for (int i = 0; i < (IN_CH * HID_CH / 4) / 256; i++)
            Ws4[tid + 256 * i] = W4[tid + 256 * i];
    }
    __syncthreads();

    int row = blockIdx.x * 32 + (tid >> 3);
    int t   = tid & 7;
    const float4* xr = (const float4*)(x + (size_t)row * IN_CH);

    float acc[8];
    #pragma unroll
    for (int j = 0; j < 8; j++) acc[j] = 0.f;

    #pragma unroll 8
    for (int k4 = 0; k4 < IN_CH / 4; k4++) {
        float4 xv = xr[k4];
        #pragma unroll
        for (int dk = 0; dk < 4; dk++) {
            float xs = (dk == 0) ? xv.x : (dk == 1) ? xv.y : (dk == 2) ? xv.z : xv.w;
            const float4* wr = (const float4*)&Ws[(k4 * 4 + dk) * HID_CH + t * 8];
            float4 w0 = wr[0], w1 = wr[1];
            acc[0] += xs * w0.x; acc[1] += xs * w0.y;
            acc[2] += xs * w0.z; acc[3] += xs * w0.w;
            acc[4] += xs * w1.x; acc[5] += xs * w1.y;
            acc[6] += xs * w1.z; acc[7] += xs * w1.w;
        }
    }

    float di  = g_dinv[row];
    float di2 = di * di;
    float4 bb0 = ((const float4*)b1)[t * 2];
    float4 bb1 = ((const float4*)b1)[t * 2 + 1];

    float4* h = (float4*)(g_h1   + (size_t)row * HID_CH + t * 8);
    float4* a = (float4*)(g_agg1 + (size_t)row * HID_CH + t * 8);
    float4 h0 = make_float4(acc[0], acc[1], acc[2], acc[3]);
    float4 h1v = make_float4(acc[4], acc[5], acc[6], acc[7]);
    h[0] = h0; h[1] = h1v;
    a[0] = make_float4(acc[0] * di2 + bb0.x, acc[1] * di2 + bb0.y,
                       acc[2] * di2 + bb0.z, acc[3] * di2 + bb0.w);
    a[1] = make_float4(acc[4] * di2 + bb1.x, acc[5] * di2 + bb1.y,
                       acc[6] * di2 + bb1.z, acc[7] * di2 + bb1.w);
}

// ---------------- scatter layer 1: agg1[dst] += h1[src] * coef ----------------
// 16 lanes per edge, float4 per lane, vector reduction (red.global.add.v4.f32).
__global__ void __launch_bounds__(256) k_scatter1() {
    int tid = blockIdx.x * 256 + threadIdx.x;     // grid sized exactly E*16
    int e = tid >> 4;
    int p = tid & 15;
    int4 ed = g_edge[e];
    float c = __int_as_float(ed.z);
    float4 v = *((const float4*)(g_h1 + ed.x) + p);
    float* dst = g_agg1 + ed.y + p * 4;
    asm volatile("red.global.add.v4.f32 [%0], {%1,%2,%3,%4};"
                 :: "l"(dst), "f"(v.x * c), "f"(v.y * c), "f"(v.z * c), "f"(v.w * c)
                 : "memory");
}

// ---------------- relu: h1 = relu(agg1) (bias already folded in) ----------------
__global__ void k_relu() {
    int i = blockIdx.x * blockDim.x + threadIdx.x;   // float4 index
    if (i >= N_NODES * (HID_CH / 4)) return;
    float4 a = ((const float4*)g_agg1)[i];
    a.x = fmaxf(a.x, 0.f); a.y = fmaxf(a.y, 0.f);
    a.z = fmaxf(a.z, 0.f); a.w = fmaxf(a.w, 0.f);
    ((float4*)g_h1)[i] = a;
}

// ---------------- GEMM2: h2 = h1 @ W2 ; out = h2*dinv^2 + b2 ----------------
__global__ void __launch_bounds__(256) k_gemm2(const float* __restrict__ W2,
                                               const float* __restrict__ b2,
                                               float* __restrict__ out) {
    __shared__ float Ws[HID_CH * OUT_CH];   // [k][32], 8KB
    int tid = threadIdx.x;
    {
        const float4* W4 = (const float4*)W2;
        float4* Ws4 = (float4*)Ws;
        #pragma unroll
        for (int i = 0; i < (HID_CH * OUT_CH / 4) / 256; i++)
            Ws4[tid + 256 * i] = W4[tid + 256 * i];
    }
    __syncthreads();

    int row = blockIdx.x * 32 + (tid >> 3);
    int t   = tid & 7;                       // 4 outputs/thread
    const float4* xr = (const float4*)(g_h1 + (size_t)row * HID_CH);

    float acc[4] = {0.f, 0.f, 0.f, 0.f};
    #pragma unroll 8
    for (int k4 = 0; k4 < HID_CH / 4; k4++) {
        float4 xv = xr[k4];
        #pragma unroll
        for (int dk = 0; dk < 4; dk++) {
            float xs = (dk == 0) ? xv.x : (dk == 1) ? xv.y : (dk == 2) ? xv.z : xv.w;
            const float4* wr = (const float4*)&Ws[(k4 * 4 + dk) * OUT_CH + t * 4];
            float4 w0 = wr[0];
            acc[0] += xs * w0.x; acc[1] += xs * w0.y;
            acc[2] += xs * w0.z; acc[3] += xs * w0.w;
        }
    }

    float di  = g_dinv[row];
    float di2 = di * di;
    float4 bb = ((const float4*)b2)[t];
    ((float4*)(g_h2 + (size_t)row * OUT_CH + t * 4))[0] =
        make_float4(acc[0], acc[1], acc[2], acc[3]);
    ((float4*)(out + (size_t)row * OUT_CH + t * 4))[0] =
        make_float4(acc[0] * di2 + bb.x, acc[1] * di2 + bb.y,
                    acc[2] * di2 + bb.z, acc[3] * di2 + bb.w);
}

// ---------------- scatter layer 2: out[dst] += h2[src] * coef ----------------
__global__ void __launch_bounds__(256) k_scatter2(float* __restrict__ out) {
    int tid = blockIdx.x * 256 + threadIdx.x;     // grid sized exactly E*8
    int e = tid >> 3;
    int p = tid & 7;
    int4 ed = g_edge[e];
    float c = __int_as_float(ed.z);
    float4 v = *((const float4*)(g_h2 + (ed.x >> 1)) + p);
    float* dst = out + (ed.y >> 1) + p * 4;
    asm volatile("red.global.add.v4.f32 [%0], {%1,%2,%3,%4};"
                 :: "l"(dst), "f"(v.x * c), "f"(v.y * c), "f"(v.z * c), "f"(v.w * c)
                 : "memory");
}

// ---------------- launch ----------------
extern "C" void kernel_launch(void* const* d_in, const int* in_sizes, int n_in,
                              void* d_out, int out_size) {
    const float* x  = (const float*)d_in[0];
    const void*  ei = d_in[1];
    const float* W1 = (const float*)d_in[2];
    const float* b1 = (const float*)d_in[3];
    const float* W2 = (const float*)d_in[4];
    const float* b2 = (const float*)d_in[5];
    float* out = (float*)d_out;

    k_detect  <<<1, 256>>>(ei, in_sizes[1]);
    k_initdeg <<<(N_NODES + 255) / 256, 256>>>();
    k_count   <<<(N_EDGES + 255) / 256, 256>>>(ei);
    k_dinv    <<<(N_NODES + 255) / 256, 256>>>();
    k_edgeprep<<<(N_EDGES + 255) / 256, 256>>>(ei);

    k_gemm1   <<<N_NODES / 32, 256>>>(x, W1, b1);
    k_scatter1<<<(N_EDGES * 16) / 256, 256>>>();
    k_relu    <<<(N_NODES * (HID_CH / 4) + 255) / 256, 256>>>();

    k_gemm2   <<<N_NODES / 32, 256>>>(W2, b2, out);
    k_scatter2<<<(N_EDGES * 8) / 256, 256>>>(out);
}

// round 3
// speedup vs baseline: 1.1339x; 1.1339x over previous
#include <cuda_runtime.h>
#include <cstdint>

#define N_NODES 100000
#define N_EDGES 1600000
#define IN_CH   128
#define HID_CH  64
#define OUT_CH  32
#define SCAN_BS 1024
#define N_SCAN_BLK ((N_NODES + SCAN_BS - 1) / SCAN_BS)   // 98

// ---------------- scratch (static __device__ — no runtime allocation) ----------------
__device__ int   g_cnt [N_NODES];          // in-degree histogram (excl. self-loop)
__device__ int   g_inc [N_NODES];          // block-local inclusive scan
__device__ int   g_bsum[N_SCAN_BLK];       // per-block totals -> scanned
__device__ int   g_off [N_NODES + 1];      // CSR row offsets
__device__ int   g_cur [N_NODES];          // fill cursors
__device__ float g_dinv[N_NODES];
__device__ int2  g_csr [N_EDGES];          // {src*HID_CH, coef_bits}, grouped by dst
__device__ float g_f1  [(size_t)N_NODES * HID_CH];   // x @ W1
__device__ float g_r1  [(size_t)N_NODES * HID_CH];   // relu(aggregated layer 1)
__device__ float g_f2  [(size_t)N_NODES * OUT_CH];   // r1 @ W2
__device__ int   g_idx64;

// ---------------- edge_index dtype detection ----------------
__global__ void k_detect(const void* ei, int n_elems) {
    __shared__ int bad;
    if (threadIdx.x == 0) bad = 0;
    __syncthreads();
    const long long* p = (const long long*)ei;
    long long m = (long long)n_elems / 2;
    if (m > 4096) m = 4096;
    for (long long i = threadIdx.x; i < m; i += blockDim.x) {
        long long v = p[i];
        if (v < 0 || v >= N_NODES) bad = 1;
    }
    __syncthreads();
    if (threadIdx.x == 0) g_idx64 = bad ? 0 : 1;
}

__device__ __forceinline__ int load_id(const void* ei, int idx) {
    if (g_idx64) return (int)((const long long*)ei)[idx];
    return ((const int*)ei)[idx];
}

// ---------------- CSR build ----------------
__global__ void k_zero() {
    int i = blockIdx.x * blockDim.x + threadIdx.x;
    if (i < N_NODES) g_cnt[i] = 0;
}

__global__ void k_hist(const void* ei) {
    int e = blockIdx.x * blockDim.x + threadIdx.x;
    if (e >= N_EDGES) return;
    atomicAdd(&g_cnt[load_id(ei, N_EDGES + e)], 1);
}

__device__ __forceinline__ int warp_iscan(int v, int lane) {
    #pragma unroll
    for (int o = 1; o < 32; o <<= 1) {
        int u = __shfl_up_sync(0xffffffffu, v, o);
        if (lane >= o) v += u;
    }
    return v;
}

__global__ void __launch_bounds__(SCAN_BS) k_scan1() {
    int t = threadIdx.x, b = blockIdx.x;
    int i = b * SCAN_BS + t;
    int v = (i < N_NODES) ? g_cnt[i] : 0;
    int lane = t & 31, w = t >> 5;
    __shared__ int ws[SCAN_BS / 32];
    int s = warp_iscan(v, lane);
    if (lane == 31) ws[w] = s;
    __syncthreads();
    if (w == 0) {
        int x = ws[lane];
        x = warp_iscan(x, lane);
        ws[lane] = x;
    }
    __syncthreads();
    if (w > 0) s += ws[w - 1];
    if (i < N_NODES) g_inc[i] = s;
    if (t == SCAN_BS - 1) g_bsum[b] = s;
}

__global__ void k_scan2() {
    int a = 0;
    for (int i = 0; i < N_SCAN_BLK; i++) { a += g_bsum[i]; g_bsum[i] = a; }
}

__global__ void __launch_bounds__(SCAN_BS) k_scan3() {
    int t = threadIdx.x, b = blockIdx.x;
    int i = b * SCAN_BS + t;
    if (i >= N_NODES) return;
    int c = g_cnt[i];
    int off = g_inc[i] - c + (b > 0 ? g_bsum[b - 1] : 0);
    g_off[i] = off;
    g_cur[i] = off;
    g_dinv[i] = rsqrtf((float)c + 1.0f);
    if (i == 0) g_off[N_NODES] = N_EDGES;
}

__global__ void k_fill(const void* ei) {
    int e = blockIdx.x * blockDim.x + threadIdx.x;
    if (e >= N_EDGES) return;
    int s = load_id(ei, e);
    int d = load_id(ei, N_EDGES + e);
    float c = g_dinv[s] * g_dinv[d];
    int pos = atomicAdd(&g_cur[d], 1);
    g_csr[pos] = make_int2(s * HID_CH, __float_as_int(c));
}

// ---------------- GEMM1: f1 = x @ W1 ----------------
__global__ void __launch_bounds__(256) k_gemm1(const float* __restrict__ x,
                                               const float* __restrict__ W1) {
    __shared__ float Ws[IN_CH * HID_CH];   // 32KB
    int tid = threadIdx.x;
    {
        const float4* W4 = (const float4*)W1;
        float4* Ws4 = (float4*)Ws;
        #pragma unroll
        for (int i = 0; i < (IN_CH * HID_CH / 4) / 256; i++)
            Ws4[tid + 256 * i] = W4[tid + 256 * i];
    }
    __syncthreads();

    int row = blockIdx.x * 32 + (tid >> 3);
    int t   = tid & 7;
    const float4* xr = (const float4*)(x + (size_t)row * IN_CH);

    float acc[8];
    #pragma unroll
    for (int j = 0; j < 8; j++) acc[j] = 0.f;

    #pragma unroll 8
    for (int k4 = 0; k4 < IN_CH / 4; k4++) {
        float4 xv = xr[k4];
        #pragma unroll
        for (int dk = 0; dk < 4; dk++) {
            float xs = (dk == 0) ? xv.x : (dk == 1) ? xv.y : (dk == 2) ? xv.z : xv.w;
            const float4* wr = (const float4*)&Ws[(k4 * 4 + dk) * HID_CH + t * 8];
            float4 w0 = wr[0], w1 = wr[1];
            acc[0] += xs * w0.x; acc[1] += xs * w0.y;
            acc[2] += xs * w0.z; acc[3] += xs * w0.w;
            acc[4] += xs * w1.x; acc[5] += xs * w1.y;
            acc[6] += xs * w1.z; acc[7] += xs * w1.w;
        }
    }
    float4* h = (float4*)(g_f1 + (size_t)row * HID_CH + t * 8);
    h[0] = make_float4(acc[0], acc[1], acc[2], acc[3]);
    h[1] = make_float4(acc[4], acc[5], acc[6], acc[7]);
}

// ---------------- aggregate layer 1 (gather) + self-loop + bias + relu ----------------
// one warp per node; lane owns channels [2*lane, 2*lane+1]
__global__ void __launch_bounds__(256) k_agg1(const float* __restrict__ b1) {
    int n = (blockIdx.x * 256 + threadIdx.x) >> 5;     // grid exact: N/8 blocks
    int lane = threadIdx.x & 31;
    int beg = g_off[n], end = g_off[n + 1];

    float ax = 0.f, ay = 0.f;
    int e = beg;
    for (; e + 4 <= end; e += 4) {
        int2 E0 = g_csr[e], E1 = g_csr[e + 1], E2 = g_csr[e + 2], E3 = g_csr[e + 3];
        float2 v0 = *(const float2*)(g_f1 + E0.x + 2 * lane);
        float2 v1 = *(const float2*)(g_f1 + E1.x + 2 * lane);
        float2 v2 = *(const float2*)(g_f1 + E2.x + 2 * lane);
        float2 v3 = *(const float2*)(g_f1 + E3.x + 2 * lane);
        float c0 = __int_as_float(E0.y), c1 = __int_as_float(E1.y);
        float c2 = __int_as_float(E2.y), c3 = __int_as_float(E3.y);
        ax += v0.x * c0 + v1.x * c1 + v2.x * c2 + v3.x * c3;
        ay += v0.y * c0 + v1.y * c1 + v2.y * c2 + v3.y * c3;
    }
    for (; e < end; e++) {
        int2 E = g_csr[e];
        float2 v = *(const float2*)(g_f1 + E.x + 2 * lane);
        float c = __int_as_float(E.y);
        ax += v.x * c;
        ay += v.y * c;
    }

    float di = g_dinv[n];
    float di2 = di * di;
    float2 self = *(const float2*)(g_f1 + (size_t)n * HID_CH + 2 * lane);
    float2 bb   = *(const float2*)(b1 + 2 * lane);
    float rx = fmaxf(ax + self.x * di2 + bb.x, 0.f);
    float ry = fmaxf(ay + self.y * di2 + bb.y, 0.f);
    *(float2*)(g_r1 + (size_t)n * HID_CH + 2 * lane) = make_float2(rx, ry);
}

// ---------------- GEMM2: f2 = r1 @ W2 ----------------
__global__ void __launch_bounds__(256) k_gemm2(const float* __restrict__ W2) {
    __shared__ float Ws[HID_CH * OUT_CH];   // 8KB
    int tid = threadIdx.x;
    {
        const float4* W4 = (const float4*)W2;
        float4* Ws4 = (float4*)Ws;
        #pragma unroll
        for (int i = 0; i < (HID_CH * OUT_CH / 4) / 256; i++)
            Ws4[tid + 256 * i] = W4[tid + 256 * i];
    }
    __syncthreads();

    int row = blockIdx.x * 32 + (tid >> 3);
    int t   = tid & 7;   // 4 outputs/thread
    const float4* xr = (const float4*)(g_r1 + (size_t)row * HID_CH);

    float acc[4] = {0.f, 0.f, 0.f, 0.f};
    #pragma unroll 8
    for (int k4 = 0; k4 < HID_CH / 4; k4++) {
        float4 xv = xr[k4];
        #pragma unroll
        for (int dk = 0; dk < 4; dk++) {
            float xs = (dk == 0) ? xv.x : (dk == 1) ? xv.y : (dk == 2) ? xv.z : xv.w;
            const float4* wr = (const float4*)&Ws[(k4 * 4 + dk) * OUT_CH + t * 4];
            float4 w0 = wr[0];
            acc[0] += xs * w0.x; acc[1] += xs * w0.y;
            acc[2] += xs * w0.z; acc[3] += xs * w0.w;
        }
    }
    ((float4*)(g_f2 + (size_t)row * OUT_CH + t * 4))[0] =
        make_float4(acc[0], acc[1], acc[2], acc[3]);
}

// ---------------- aggregate layer 2 (gather) + self-loop + bias -> out ----------------
// one warp per node; lane owns channel lane
__global__ void __launch_bounds__(256) k_agg2(const float* __restrict__ b2,
                                              float* __restrict__ out) {
    int n = (blockIdx.x * 256 + threadIdx.x) >> 5;
    int lane = threadIdx.x & 31;
    int beg = g_off[n], end = g_off[n + 1];

    float a = 0.f;
    int e = beg;
    for (; e + 4 <= end; e += 4) {
        int2 E0 = g_csr[e], E1 = g_csr[e + 1], E2 = g_csr[e + 2], E3 = g_csr[e + 3];
        float v0 = g_f2[(E0.x >> 1) + lane];
        float v1 = g_f2[(E1.x >> 1) + lane];
        float v2 = g_f2[(E2.x >> 1) + lane];
        float v3 = g_f2[(E3.x >> 1) + lane];
        a += v0 * __int_as_float(E0.y) + v1 * __int_as_float(E1.y)
           + v2 * __int_as_float(E2.y) + v3 * __int_as_float(E3.y);
    }
    for (; e < end; e++) {
        int2 E = g_csr[e];
        a += g_f2[(E.x >> 1) + lane] * __int_as_float(E.y);
    }

    float di = g_dinv[n];
    float self = g_f2[(size_t)n * OUT_CH + lane];
    out[(size_t)n * OUT_CH + lane] = a + self * di * di + b2[lane];
}

// ---------------- launch ----------------
extern "C" void kernel_launch(void* const* d_in, const int* in_sizes, int n_in,
                              void* d_out, int out_size) {
    const float* x  = (const float*)d_in[0];
    const void*  ei = d_in[1];
    const float* W1 = (const float*)d_in[2];
    const float* b1 = (const float*)d_in[3];
    const float* W2 = (const float*)d_in[4];
    const float* b2 = (const float*)d_in[5];
    float* out = (float*)d_out;

    k_detect<<<1, 256>>>(ei, in_sizes[1]);
    k_zero  <<<(N_NODES + 255) / 256, 256>>>();
    k_hist  <<<N_EDGES / 256, 256>>>(ei);
    k_scan1 <<<N_SCAN_BLK, SCAN_BS>>>();
    k_scan2 <<<1, 1>>>();
    k_scan3 <<<N_SCAN_BLK, SCAN_BS>>>();
    k_fill  <<<N_EDGES / 256, 256>>>(ei);

    k_gemm1 <<<N_NODES / 32, 256>>>(x, W1);
    k_agg1  <<<N_NODES / 8, 256>>>(b1);
    k_gemm2 <<<N_NODES / 32, 256>>>(W2);
    k_agg2  <<<N_NODES / 8, 256>>>(b2, out);
}

// round 4
// speedup vs baseline: 1.2035x; 1.0614x over previous
#include <cuda_runtime.h>
#include <cuda_fp16.h>
#include <cstdint>

#define N_NODES 100000
#define N_EDGES 1600000
#define IN_CH   128
#define HID_CH  64
#define OUT_CH  32
#define SCAN_BS 1024
#define N_SCAN_BLK ((N_NODES + SCAN_BS - 1) / SCAN_BS)   // 98

// ---------------- scratch (static __device__ — no runtime allocation) ----------------
__device__ int     g_cnt [N_NODES];
__device__ int     g_inc [N_NODES];
__device__ int     g_bsum[N_SCAN_BLK];
__device__ int     g_off [N_NODES + 1];
__device__ int     g_cur [N_NODES];
__device__ float   g_dinv[N_NODES];
__device__ int2    g_csr [N_EDGES];                         // {src*HID_CH, coef_bits}
__device__ __half2 g_f1h [(size_t)N_NODES * (HID_CH / 2)];  // x @ W1, fp16
__device__ float   g_r1  [(size_t)N_NODES * HID_CH];        // relu(agg layer 1), fp32
__device__ __half  g_f2h [(size_t)N_NODES * OUT_CH];        // r1 @ W2, fp16
__device__ int     g_idx64;

// ---------------- dtype detect + histogram zero (merged) ----------------
__global__ void k_detect_zero(const void* ei, int n_elems) {
    int i = blockIdx.x * blockDim.x + threadIdx.x;
    if (i < N_NODES) g_cnt[i] = 0;
    if (blockIdx.x == 0) {
        __shared__ int bad;
        if (threadIdx.x == 0) bad = 0;
        __syncthreads();
        const long long* p = (const long long*)ei;
        long long m = (long long)n_elems / 2;
        if (m > 2048) m = 2048;
        for (long long j = threadIdx.x; j < m; j += blockDim.x) {
            long long v = p[j];
            if (v < 0 || v >= N_NODES) bad = 1;
        }
        __syncthreads();
        if (threadIdx.x == 0) g_idx64 = bad ? 0 : 1;
    }
}

__device__ __forceinline__ int load_id(const void* ei, int idx) {
    if (g_idx64) return (int)((const long long*)ei)[idx];
    return ((const int*)ei)[idx];
}

// ---------------- CSR build ----------------
__global__ void k_hist(const void* ei) {
    int e = blockIdx.x * blockDim.x + threadIdx.x;
    if (e >= N_EDGES) return;
    atomicAdd(&g_cnt[load_id(ei, N_EDGES + e)], 1);
}

__device__ __forceinline__ int warp_iscan(int v, int lane) {
    #pragma unroll
    for (int o = 1; o < 32; o <<= 1) {
        int u = __shfl_up_sync(0xffffffffu, v, o);
        if (lane >= o) v += u;
    }
    return v;
}

__global__ void __launch_bounds__(SCAN_BS) k_scan1() {
    int t = threadIdx.x, b = blockIdx.x;
    int i = b * SCAN_BS + t;
    int v = (i < N_NODES) ? g_cnt[i] : 0;
    int lane = t & 31, w = t >> 5;
    __shared__ int ws[SCAN_BS / 32];
    int s = warp_iscan(v, lane);
    if (lane == 31) ws[w] = s;
    __syncthreads();
    if (w == 0) ws[lane] = warp_iscan(ws[lane], lane);
    __syncthreads();
    if (w > 0) s += ws[w - 1];
    if (i < N_NODES) g_inc[i] = s;
    if (t == SCAN_BS - 1) g_bsum[b] = s;
}

// one-warp scan of the 98 block totals (was a single-thread serial chain)
__global__ void k_scan2() {
    int lane = threadIdx.x;
    int carry = 0;
    #pragma unroll
    for (int c = 0; c < (N_SCAN_BLK + 31) / 32; c++) {
        int i = c * 32 + lane;
        int v = (i < N_SCAN_BLK) ? g_bsum[i] : 0;
        int s = warp_iscan(v, lane);
        if (i < N_SCAN_BLK) g_bsum[i] = s + carry;
        carry += __shfl_sync(0xffffffffu, s, 31);
    }
}

__global__ void __launch_bounds__(SCAN_BS) k_scan3() {
    int t = threadIdx.x, b = blockIdx.x;
    int i = b * SCAN_BS + t;
    if (i >= N_NODES) return;
    int c = g_cnt[i];
    int off = g_inc[i] - c + (b > 0 ? g_bsum[b - 1] : 0);
    g_off[i] = off;
    g_cur[i] = off;
    g_dinv[i] = rsqrtf((float)c + 1.0f);
    if (i == 0) g_off[N_NODES] = N_EDGES;
}

__global__ void k_fill(const void* ei) {
    int e = blockIdx.x * blockDim.x + threadIdx.x;
    if (e >= N_EDGES) return;
    int s = load_id(ei, e);
    int d = load_id(ei, N_EDGES + e);
    float c = g_dinv[s] * g_dinv[d];
    int pos = atomicAdd(&g_cur[d], 1);
    g_csr[pos] = make_int2(s * HID_CH, __float_as_int(c));
}

// ---------------- GEMM1: f1h = fp16(x @ W1) ----------------
__global__ void __launch_bounds__(256) k_gemm1(const float* __restrict__ x,
                                               const float* __restrict__ W1) {
    __shared__ float Ws[IN_CH * HID_CH];   // 32KB
    int tid = threadIdx.x;
    {
        const float4* W4 = (const float4*)W1;
        float4* Ws4 = (float4*)Ws;
        #pragma unroll
        for (int i = 0; i < (IN_CH * HID_CH / 4) / 256; i++)
            Ws4[tid + 256 * i] = W4[tid + 256 * i];
    }
    __syncthreads();

    int row = blockIdx.x * 32 + (tid >> 3);
    int t   = tid & 7;
    const float4* xr = (const float4*)(x + (size_t)row * IN_CH);

    float acc[8];
    #pragma unroll
    for (int j = 0; j < 8; j++) acc[j] = 0.f;

    #pragma unroll 8
    for (int k4 = 0; k4 < IN_CH / 4; k4++) {
        float4 xv = xr[k4];
        #pragma unroll
        for (int dk = 0; dk < 4; dk++) {
            float xs = (dk == 0) ? xv.x : (dk == 1) ? xv.y : (dk == 2) ? xv.z : xv.w;
            const float4* wr = (const float4*)&Ws[(k4 * 4 + dk) * HID_CH + t * 8];
            float4 w0 = wr[0], w1 = wr[1];
            acc[0] += xs * w0.x; acc[1] += xs * w0.y;
            acc[2] += xs * w0.z; acc[3] += xs * w0.w;
            acc[4] += xs * w1.x; acc[5] += xs * w1.y;
            acc[6] += xs * w1.z; acc[7] += xs * w1.w;
        }
    }
    // pack 8 fp32 -> 4 half2 -> one 16B store
    __half2 h0 = __floats2half2_rn(acc[0], acc[1]);
    __half2 h1 = __floats2half2_rn(acc[2], acc[3]);
    __half2 h2 = __floats2half2_rn(acc[4], acc[5]);
    __half2 h3 = __floats2half2_rn(acc[6], acc[7]);
    uint4 pk = make_uint4(*(uint32_t*)&h0, *(uint32_t*)&h1,
                          *(uint32_t*)&h2, *(uint32_t*)&h3);
    *((uint4*)(g_f1h + (size_t)row * (HID_CH / 2)) + t) = pk;
}

// ---------------- agg layer 1 (fp16 gather) + self + bias + relu -> r1 fp32 ----------------
// one warp per node; lane owns channels {2*lane, 2*lane+1} (one half2)
__global__ void __launch_bounds__(256) k_agg1(const float* __restrict__ b1) {
    int n = (blockIdx.x * 256 + threadIdx.x) >> 5;
    int lane = threadIdx.x & 31;
    int beg = g_off[n], end = g_off[n + 1];

    float ax = 0.f, ay = 0.f;
    int e = beg;
    for (; e + 4 <= end; e += 4) {
        int2 E0 = g_csr[e], E1 = g_csr[e + 1], E2 = g_csr[e + 2], E3 = g_csr[e + 3];
        float2 v0 = __half22float2(g_f1h[(E0.x >> 1) + lane]);
        float2 v1 = __half22float2(g_f1h[(E1.x >> 1) + lane]);
        float2 v2 = __half22float2(g_f1h[(E2.x >> 1) + lane]);
        float2 v3 = __half22float2(g_f1h[(E3.x >> 1) + lane]);
        float c0 = __int_as_float(E0.y), c1 = __int_as_float(E1.y);
        float c2 = __int_as_float(E2.y), c3 = __int_as_float(E3.y);
        ax += v0.x * c0 + v1.x * c1 + v2.x * c2 + v3.x * c3;
        ay += v0.y * c0 + v1.y * c1 + v2.y * c2 + v3.y * c3;
    }
    for (; e < end; e++) {
        int2 E = g_csr[e];
        float2 v = __half22float2(g_f1h[(E.x >> 1) + lane]);
        float c = __int_as_float(E.y);
        ax += v.x * c;
        ay += v.y * c;
    }

    float di = g_dinv[n];
    float di2 = di * di;
    float2 self = __half22float2(g_f1h[(size_t)n * (HID_CH / 2) + lane]);
    float2 bb   = *(const float2*)(b1 + 2 * lane);
    float rx = fmaxf(ax + self.x * di2 + bb.x, 0.f);
    float ry = fmaxf(ay + self.y * di2 + bb.y, 0.f);
    *(float2*)(g_r1 + (size_t)n * HID_CH + 2 * lane) = make_float2(rx, ry);
}

// ---------------- GEMM2: f2h = fp16(r1 @ W2) ----------------
__global__ void __launch_bounds__(256) k_gemm2(const float* __restrict__ W2) {
    __shared__ float Ws[HID_CH * OUT_CH];   // 8KB
    int tid = threadIdx.x;
    {
        const float4* W4 = (const float4*)W2;
        float4* Ws4 = (float4*)Ws;
        #pragma unroll
        for (int i = 0; i < (HID_CH * OUT_CH / 4) / 256; i++)
            Ws4[tid + 256 * i] = W4[tid + 256 * i];
    }
    __syncthreads();

    int row = blockIdx.x * 32 + (tid >> 3);
    int t   = tid & 7;   // 4 outputs/thread
    const float4* xr = (const float4*)(g_r1 + (size_t)row * HID_CH);

    float acc[4] = {0.f, 0.f, 0.f, 0.f};
    #pragma unroll 8
    for (int k4 = 0; k4 < HID_CH / 4; k4++) {
        float4 xv = xr[k4];
        #pragma unroll
        for (int dk = 0; dk < 4; dk++) {
            float xs = (dk == 0) ? xv.x : (dk == 1) ? xv.y : (dk == 2) ? xv.z : xv.w;
            const float4* wr = (const float4*)&Ws[(k4 * 4 + dk) * OUT_CH + t * 4];
            float4 w0 = wr[0];
            acc[0] += xs * w0.x; acc[1] += xs * w0.y;
            acc[2] += xs * w0.z; acc[3] += xs * w0.w;
        }
    }
    __half2 h0 = __floats2half2_rn(acc[0], acc[1]);
    __half2 h1 = __floats2half2_rn(acc[2], acc[3]);
    uint2 pk = make_uint2(*(uint32_t*)&h0, *(uint32_t*)&h1);
    *((uint2*)(g_f2h + (size_t)row * OUT_CH) + t) = pk;
}

// ---------------- agg layer 2 (fp16 gather) + self + bias -> out fp32 ----------------
// one warp per node; lane owns channel `lane` (OUT_CH=32)
__global__ void __launch_bounds__(256) k_agg2(const float* __restrict__ b2,
                                              float* __restrict__ out) {
    int n = (blockIdx.x * 256 + threadIdx.x) >> 5;
    int lane = threadIdx.x & 31;
    int beg = g_off[n], end = g_off[n + 1];

    float a = 0.f;
    int e = beg;
    for (; e + 4 <= end; e += 4) {
        int2 E0 = g_csr[e], E1 = g_csr[e + 1], E2 = g_csr[e + 2], E3 = g_csr[e + 3];
        float v0 = __half2float(g_f2h[(E0.x >> 1) + lane]);
        float v1 = __half2float(g_f2h[(E1.x >> 1) + lane]);
        float v2 = __half2float(g_f2h[(E2.x >> 1) + lane]);
        float v3 = __half2float(g_f2h[(E3.x >> 1) + lane]);
        a += v0 * __int_as_float(E0.y) + v1 * __int_as_float(E1.y)
           + v2 * __int_as_float(E2.y) + v3 * __int_as_float(E3.y);
    }
    for (; e < end; e++) {
        int2 E = g_csr[e];
        a += __half2float(g_f2h[(E.x >> 1) + lane]) * __int_as_float(E.y);
    }

    float di = g_dinv[n];
    float self = __half2float(g_f2h[(size_t)n * OUT_CH + lane]);
    out[(size_t)n * OUT_CH + lane] = a + self * di * di + b2[lane];
}

// ---------------- launch ----------------
extern "C" void kernel_launch(void* const* d_in, const int* in_sizes, int n_in,
                              void* d_out, int out_size) {
    const float* x  = (const float*)d_in[0];
    const void*  ei = d_in[1];
    const float* W1 = (const float*)d_in[2];
    const float* b1 = (const float*)d_in[3];
    const float* W2 = (const float*)d_in[4];
    const float* b2 = (const float*)d_in[5];
    float* out = (float*)d_out;

    k_detect_zero<<<(N_NODES + 255) / 256, 256>>>(ei, in_sizes[1]);
    k_hist  <<<N_EDGES / 256, 256>>>(ei);
    k_scan1 <<<N_SCAN_BLK, SCAN_BS>>>();
    k_scan2 <<<1, 32>>>();
    k_scan3 <<<N_SCAN_BLK, SCAN_BS>>>();
    k_fill  <<<N_EDGES / 256, 256>>>(ei);

    k_gemm1 <<<N_NODES / 32, 256>>>(x, W1);
    k_agg1  <<<N_NODES / 8, 256>>>(b1);
    k_gemm2 <<<N_NODES / 32, 256>>>(W2);
    k_agg2  <<<N_NODES / 8, 256>>>(b2, out);
}

// round 5
// speedup vs baseline: 1.9267x; 1.6009x over previous
#include <cuda_runtime.h>
#include <cuda_fp16.h>
#include <cstdint>

#define N_NODES 100000
#define N_EDGES 1600000
#define IN_CH   128
#define HID_CH  64
#define OUT_CH  32
#define SCAN_BS 1024
#define N_SCAN_BLK ((N_NODES + SCAN_BS - 1) / SCAN_BS)   // 98
#define GEMM_ROWS 128                                     // rows per GEMM block
#define N_GEMM_BLK ((N_NODES + GEMM_ROWS - 1) / GEMM_ROWS)

typedef unsigned long long u64;

// packed f32x2 fma: d = a*b + d  (2 FMAs/instr on sm_103a)
#define FMA_X2(d, a, b) \
    asm("fma.rn.f32x2 %0, %1, %2, %0;" : "+l"(d) : "l"(a), "l"(b))
#define DUP_X2(out, f) \
    asm("mov.b64 %0, {%1, %1};" : "=l"(out) : "f"(f))
#define UNPK_X2(lo, hi, in) \
    asm("mov.b64 {%0, %1}, %2;" : "=f"(lo), "=f"(hi) : "l"(in))

// ---------------- scratch ----------------
__device__ int     g_cnt [N_NODES];
__device__ int     g_inc [N_NODES];
__device__ int     g_bsum[N_SCAN_BLK];
__device__ int     g_off [N_NODES + 1];
__device__ int     g_cur [N_NODES];
__device__ float   g_dinv[N_NODES];
__device__ int2    g_csr [N_EDGES];                         // {src*HID_CH, coef_bits}
__device__ __half2 g_f1h [(size_t)N_NODES * (HID_CH / 2)];  // x @ W1, fp16
__device__ float   g_r1  [(size_t)N_NODES * HID_CH];        // relu(agg layer 1), fp32
__device__ __half  g_f2h [(size_t)N_NODES * OUT_CH];        // r1 @ W2, fp16
__device__ int     g_idx64;

// ---------------- dtype detect + histogram zero ----------------
__global__ void k_detect_zero(const void* ei, int n_elems) {
    int i = blockIdx.x * blockDim.x + threadIdx.x;
    if (i < N_NODES) g_cnt[i] = 0;
    if (blockIdx.x == 0) {
        __shared__ int bad;
        if (threadIdx.x == 0) bad = 0;
        __syncthreads();
        const long long* p = (const long long*)ei;
        long long m = (long long)n_elems / 2;
        if (m > 2048) m = 2048;
        for (long long j = threadIdx.x; j < m; j += blockDim.x) {
            long long v = p[j];
            if (v < 0 || v >= N_NODES) bad = 1;
        }
        __syncthreads();
        if (threadIdx.x == 0) g_idx64 = bad ? 0 : 1;
    }
}

__device__ __forceinline__ int load_id(const void* ei, int idx) {
    if (g_idx64) return (int)((const long long*)ei)[idx];
    return ((const int*)ei)[idx];
}

// ---------------- CSR build ----------------
__global__ void k_hist(const void* ei) {
    int e = blockIdx.x * blockDim.x + threadIdx.x;
    if (e >= N_EDGES) return;
    atomicAdd(&g_cnt[load_id(ei, N_EDGES + e)], 1);
}

__device__ __forceinline__ int warp_iscan(int v, int lane) {
    #pragma unroll
    for (int o = 1; o < 32; o <<= 1) {
        int u = __shfl_up_sync(0xffffffffu, v, o);
        if (lane >= o) v += u;
    }
    return v;
}

__global__ void __launch_bounds__(SCAN_BS) k_scan1() {
    int t = threadIdx.x, b = blockIdx.x;
    int i = b * SCAN_BS + t;
    int v = (i < N_NODES) ? g_cnt[i] : 0;
    int lane = t & 31, w = t >> 5;
    __shared__ int ws[SCAN_BS / 32];
    int s = warp_iscan(v, lane);
    if (lane == 31) ws[w] = s;
    __syncthreads();
    if (w == 0) ws[lane] = warp_iscan(ws[lane], lane);
    __syncthreads();
    if (w > 0) s += ws[w - 1];
    if (i < N_NODES) g_inc[i] = s;
    if (t == SCAN_BS - 1) g_bsum[b] = s;
}

// scan of block totals folded in: each block warp-reduces its bsum prefix
__global__ void __launch_bounds__(SCAN_BS) k_scan3() {
    int t = threadIdx.x, b = blockIdx.x;
    __shared__ int pfx;
    if (t < 32) {
        int s = 0;
        for (int i = t; i < b; i += 32) s += g_bsum[i];
        #pragma unroll
        for (int o = 16; o; o >>= 1) s += __shfl_down_sync(0xffffffffu, s, o);
        if (t == 0) pfx = s;
    }
    __syncthreads();
    int i = b * SCAN_BS + t;
    if (i >= N_NODES) return;
    int c = g_cnt[i];
    int off = g_inc[i] - c + pfx;
    g_off[i] = off;
    g_cur[i] = off;
    g_dinv[i] = rsqrtf((float)c + 1.0f);
    if (i == 0) g_off[N_NODES] = N_EDGES;
}

__global__ void k_fill(const void* ei) {
    int e = blockIdx.x * blockDim.x + threadIdx.x;
    if (e >= N_EDGES) return;
    int s = load_id(ei, e);
    int d = load_id(ei, N_EDGES + e);
    float c = g_dinv[s] * g_dinv[d];
    int pos = atomicAdd(&g_cur[d], 1);
    g_csr[pos] = make_int2(s * HID_CH, __float_as_int(c));
}

// ---------------- GEMM1: f1h = fp16(x @ W1) ----------------
// 256 threads; tid&7 = col group (8 cols), tid>>3 = row group (4 rows) -> 128 rows/block.
// W pairs load directly from smem as 64-bit words (adjacent floats = f32x2 pair).
__global__ void __launch_bounds__(256) k_gemm1(const float* __restrict__ x,
                                               const float* __restrict__ W1) {
    __shared__ float Ws[IN_CH * HID_CH];   // 32KB, [k][64]
    int tid = threadIdx.x;
    {
        const float4* W4 = (const float4*)W1;
        float4* Ws4 = (float4*)Ws;
        #pragma unroll
        for (int i = 0; i < (IN_CH * HID_CH / 4) / 256; i++)
            Ws4[tid + 256 * i] = W4[tid + 256 * i];
    }
    __syncthreads();

    int t    = tid & 7;
    int row0 = blockIdx.x * GEMM_ROWS + (tid >> 3) * 4;
    bool v0 = row0     < N_NODES, v1 = row0 + 1 < N_NODES;
    bool v2 = row0 + 2 < N_NODES, v3 = row0 + 3 < N_NODES;

    u64 acc[4][4];
    #pragma unroll
    for (int r = 0; r < 4; r++)
        #pragma unroll
        for (int j = 0; j < 4; j++) acc[r][j] = 0ull;

    const float4* xr = (const float4*)(x + (size_t)row0 * IN_CH);
    const float4 z4 = make_float4(0.f, 0.f, 0.f, 0.f);

    #pragma unroll 4
    for (int k4 = 0; k4 < IN_CH / 4; k4++) {
        float4 xa0 = v0 ? xr[k4]                    : z4;
        float4 xa1 = v1 ? xr[k4 + IN_CH / 4]        : z4;
        float4 xa2 = v2 ? xr[k4 + 2 * (IN_CH / 4)]  : z4;
        float4 xa3 = v3 ? xr[k4 + 3 * (IN_CH / 4)]  : z4;
        #pragma unroll
        for (int dk = 0; dk < 4; dk++) {
            float s0 = (dk == 0) ? xa0.x : (dk == 1) ? xa0.y : (dk == 2) ? xa0.z : xa0.w;
            float s1 = (dk == 0) ? xa1.x : (dk == 1) ? xa1.y : (dk == 2) ? xa1.z : xa1.w;
            float s2 = (dk == 0) ? xa2.x : (dk == 1) ? xa2.y : (dk == 2) ? xa2.z : xa2.w;
            float s3 = (dk == 0) ? xa3.x : (dk == 1) ? xa3.y : (dk == 2) ? xa3.z : xa3.w;
            u64 xp[4];
            DUP_X2(xp[0], s0); DUP_X2(xp[1], s1);
            DUP_X2(xp[2], s2); DUP_X2(xp[3], s3);
            const u64* wr = (const u64*)&Ws[(k4 * 4 + dk) * HID_CH + t * 8];
            u64 w0 = wr[0], w1 = wr[1], w2 = wr[2], w3 = wr[3];
            #pragma unroll
            for (int r = 0; r < 4; r++) {
                FMA_X2(acc[r][0], xp[r], w0);
                FMA_X2(acc[r][1], xp[r], w1);
                FMA_X2(acc[r][2], xp[r], w2);
                FMA_X2(acc[r][3], xp[r], w3);
            }
        }
    }

    #pragma unroll
    for (int r = 0; r < 4; r++) {
        int row = row0 + r;
        if (row >= N_NODES) break;
        float a0, a1, a2, a3, a4, a5, a6, a7;
        UNPK_X2(a0, a1, acc[r][0]); UNPK_X2(a2, a3, acc[r][1]);
        UNPK_X2(a4, a5, acc[r][2]); UNPK_X2(a6, a7, acc[r][3]);
        __half2 h0 = __floats2half2_rn(a0, a1);
        __half2 h1 = __floats2half2_rn(a2, a3);
        __half2 h2 = __floats2half2_rn(a4, a5);
        __half2 h3 = __floats2half2_rn(a6, a7);
        uint4 pk = make_uint4(*(uint32_t*)&h0, *(uint32_t*)&h1,
                              *(uint32_t*)&h2, *(uint32_t*)&h3);
        *((uint4*)(g_f1h + (size_t)row * (HID_CH / 2)) + t) = pk;
    }
}

// ---------------- agg layer 1 (fp16 gather) + self + bias + relu -> r1 fp32 ----------------
__global__ void __launch_bounds__(256) k_agg1(const float* __restrict__ b1) {
    int n = (blockIdx.x * 256 + threadIdx.x) >> 5;
    int lane = threadIdx.x & 31;
    int beg = g_off[n], end = g_off[n + 1];

    float ax = 0.f, ay = 0.f;
    int e = beg;
    for (; e + 4 <= end; e += 4) {
        int2 E0 = g_csr[e], E1 = g_csr[e + 1], E2 = g_csr[e + 2], E3 = g_csr[e + 3];
        float2 v0 = __half22float2(g_f1h[(E0.x >> 1) + lane]);
        float2 v1 = __half22float2(g_f1h[(E1.x >> 1) + lane]);
        float2 v2 = __half22float2(g_f1h[(E2.x >> 1) + lane]);
        float2 v3 = __half22float2(g_f1h[(E3.x >> 1) + lane]);
        float c0 = __int_as_float(E0.y), c1 = __int_as_float(E1.y);
        float c2 = __int_as_float(E2.y), c3 = __int_as_float(E3.y);
        ax += v0.x * c0 + v1.x * c1 + v2.x * c2 + v3.x * c3;
        ay += v0.y * c0 + v1.y * c1 + v2.y * c2 + v3.y * c3;
    }
    for (; e < end; e++) {
        int2 E = g_csr[e];
        float2 v = __half22float2(g_f1h[(E.x >> 1) + lane]);
        float c = __int_as_float(E.y);
        ax += v.x * c;
        ay += v.y * c;
    }

    float di = g_dinv[n];
    float di2 = di * di;
    float2 self = __half22float2(g_f1h[(size_t)n * (HID_CH / 2) + lane]);
    float2 bb   = *(const float2*)(b1 + 2 * lane);
    float rx = fmaxf(ax + self.x * di2 + bb.x, 0.f);
    float ry = fmaxf(ay + self.y * di2 + bb.y, 0.f);
    *(float2*)(g_r1 + (size_t)n * HID_CH + 2 * lane) = make_float2(rx, ry);
}

// ---------------- GEMM2: f2h = fp16(r1 @ W2) ----------------
// tid&7 = col group (4 cols = 2 pairs), tid>>3 row group (4 rows) -> 128 rows/block
__global__ void __launch_bounds__(256) k_gemm2(const float* __restrict__ W2) {
    __shared__ float Ws[HID_CH * OUT_CH];   // 8KB, [k][32]
    int tid = threadIdx.x;
    {
        const float4* W4 = (const float4*)W2;
        float4* Ws4 = (float4*)Ws;
        #pragma unroll
        for (int i = 0; i < (HID_CH * OUT_CH / 4) / 256; i++)
            Ws4[tid + 256 * i] = W4[tid + 256 * i];
    }
    __syncthreads();

    int t    = tid & 7;
    int row0 = blockIdx.x * GEMM_ROWS + (tid >> 3) * 4;
    bool v0 = row0     < N_NODES, v1 = row0 + 1 < N_NODES;
    bool v2 = row0 + 2 < N_NODES, v3 = row0 + 3 < N_NODES;

    u64 acc[4][2];
    #pragma unroll
    for (int r = 0; r < 4; r++) { acc[r][0] = 0ull; acc[r][1] = 0ull; }

    const float4* xr = (const float4*)(g_r1 + (size_t)row0 * HID_CH);
    const float4 z4 = make_float4(0.f, 0.f, 0.f, 0.f);

    #pragma unroll 4
    for (int k4 = 0; k4 < HID_CH / 4; k4++) {
        float4 xa0 = v0 ? xr[k4]                     : z4;
        float4 xa1 = v1 ? xr[k4 + HID_CH / 4]        : z4;
        float4 xa2 = v2 ? xr[k4 + 2 * (HID_CH / 4)]  : z4;
        float4 xa3 = v3 ? xr[k4 + 3 * (HID_CH / 4)]  : z4;
        #pragma unroll
        for (int dk = 0; dk < 4; dk++) {
            float s0 = (dk == 0) ? xa0.x : (dk == 1) ? xa0.y : (dk == 2) ? xa0.z : xa0.w;
            float s1 = (dk == 0) ? xa1.x : (dk == 1) ? xa1.y : (dk == 2) ? xa1.z : xa1.w;
            float s2 = (dk == 0) ? xa2.x : (dk == 1) ? xa2.y : (dk == 2) ? xa2.z : xa2.w;
            float s3 = (dk == 0) ? xa3.x : (dk == 1) ? xa3.y : (dk == 2) ? xa3.z : xa3.w;
            u64 xp[4];
            DUP_X2(xp[0], s0); DUP_X2(xp[1], s1);
            DUP_X2(xp[2], s2); DUP_X2(xp[3], s3);
            const u64* wr = (const u64*)&Ws[(k4 * 4 + dk) * OUT_CH + t * 4];
            u64 w0 = wr[0], w1 = wr[1];
            #pragma unroll
            for (int r = 0; r < 4; r++) {
                FMA_X2(acc[r][0], xp[r], w0);
                FMA_X2(acc[r][1], xp[r], w1);
            }
        }
    }

    #pragma unroll
    for (int r = 0; r < 4; r++) {
        int row = row0 + r;
        if (row >= N_NODES) break;
        float a0, a1, a2, a3;
        UNPK_X2(a0, a1, acc[r][0]); UNPK_X2(a2, a3, acc[r][1]);
        __half2 h0 = __floats2half2_rn(a0, a1);
        __half2 h1 = __floats2half2_rn(a2, a3);
        uint2 pk = make_uint2(*(uint32_t*)&h0, *(uint32_t*)&h1);
        *((uint2*)(g_f2h + (size_t)row * OUT_CH) + t) = pk;
    }
}

// ---------------- agg layer 2 (fp16 gather) + self + bias -> out fp32 ----------------
__global__ void __launch_bounds__(256) k_agg2(const float* __restrict__ b2,
                                              float* __restrict__ out) {
    int n = (blockIdx.x * 256 + threadIdx.x) >> 5;
    int lane = threadIdx.x & 31;
    int beg = g_off[n], end = g_off[n + 1];

    float a = 0.f;
    int e = beg;
    for (; e + 4 <= end; e += 4) {
        int2 E0 = g_csr[e], E1 = g_csr[e + 1], E2 = g_csr[e + 2], E3 = g_csr[e + 3];
        float v0 = __half2float(g_f2h[(E0.x >> 1) + lane]);
        float v1 = __half2float(g_f2h[(E1.x >> 1) + lane]);
        float v2 = __half2float(g_f2h[(E2.x >> 1) + lane]);
        float v3 = __half2float(g_f2h[(E3.x >> 1) + lane]);
        a += v0 * __int_as_float(E0.y) + v1 * __int_as_float(E1.y)
           + v2 * __int_as_float(E2.y) + v3 * __int_as_float(E3.y);
    }
    for (; e < end; e++) {
        int2 E = g_csr[e];
        a += __half2float(g_f2h[(E.x >> 1) + lane]) * __int_as_float(E.y);
    }

    float di = g_dinv[n];
    float self = __half2float(g_f2h[(size_t)n * OUT_CH + lane]);
    out[(size_t)n * OUT_CH + lane] = a + self * di * di + b2[lane];
}

// ---------------- launch ----------------
extern "C" void kernel_launch(void* const* d_in, const int* in_sizes, int n_in,
                              void* d_out, int out_size) {
    const float* x  = (const float*)d_in[0];
    const void*  ei = d_in[1];
    const float* W1 = (const float*)d_in[2];
    const float* b1 = (const float*)d_in[3];
    const float* W2 = (const float*)d_in[4];
    const float* b2 = (const float*)d_in[5];
    float* out = (float*)d_out;

    k_detect_zero<<<(N_NODES + 255) / 256, 256>>>(ei, in_sizes[1]);
    k_hist  <<<N_EDGES / 256, 256>>>(ei);
    k_scan1 <<<N_SCAN_BLK, SCAN_BS>>>();
    k_scan3 <<<N_SCAN_BLK, SCAN_BS>>>();
    k_fill  <<<N_EDGES / 256, 256>>>(ei);

    k_gemm1 <<<N_GEMM_BLK, 256>>>(x, W1);
    k_agg1  <<<N_NODES / 8, 256>>>(b1);
    k_gemm2 <<<N_GEMM_BLK, 256>>>(W2);
    k_agg2  <<<N_NODES / 8, 256>>>(b2, out);
}